// round 15
// baseline (speedup 1.0000x reference)
#include <cuda_runtime.h>
#include <math.h>

// Problem constants
#define M_TOT 32768            // 512*64 matrices
#define BLOCKS 1024
#define THREADS 128
#define WPB 4
#define NWARPS (BLOCKS * WPB)  // 4096 warps -> 8 matrices each
#define TS 36                  // tile row stride in floats (16B-aligned, conflict-free)
#define TS4 9                  // tile row stride in float4
#define PSTRIDE 33             // stats entry stride
#define PART_ENTRIES (32 * PSTRIDE)   // 1056

// Scratch (static device arrays; no runtime allocation allowed)
__device__ float g_L[(size_t)M_TOT * 1024];        // Cholesky factors, COLUMN-major per matrix
__device__ float g_part[PART_ENTRIES * BLOCKS];    // per-block partials, [entry][block]
__device__ float g_sums[PART_ENTRIES];
__device__ float g_stats[1025];                    // mean[32*32] (diag slot = logd mean) + factor

// ---------------------------------------------------------------------------
// Pass 1: coalesced load + smem transpose, warp-per-matrix Cholesky with
// deferred normalization (raw column broadcast through smem; no shfl on the
// critical path). Unchanged from R14 (measured).
// ---------------------------------------------------------------------------
__global__ void __launch_bounds__(THREADS) chol_pass1(const float* __restrict__ X) {
    __shared__ float4 sbuf[WPB * 304];   // per warp: 288 tile f4 + 16 colbuf f4
    const int lane = threadIdx.x & 31;
    const int wl   = threadIdx.x >> 5;
    float4* tile = sbuf + wl * 304;
    float*  colf = (float*)(tile + 288);
    const int gw = blockIdx.x * WPB + wl;

    float acc[32];
#pragma unroll
    for (int j = 0; j < 32; j++) acc[j] = 0.f;
    float accsq = 0.f;

    for (int m = gw; m < M_TOT; m += NWARPS) {
        // coalesced load of X, transpose through smem (row-major tile)
        const float4* xs = (const float4*)(X + (size_t)m * 1024);
#pragma unroll
        for (int q = 0; q < 8; q++) {
            float4 v = xs[q * 32 + lane];
            tile[(4 * q + (lane >> 3)) * TS4 + (lane & 7)] = v;
        }
        __syncwarp();
        // own row into registers (conflict-free LDS.128)
        float a[32];
#pragma unroll
        for (int q = 0; q < 8; q++) {
            float4 v = tile[lane * TS4 + q];
            a[4*q+0] = v.x; a[4*q+1] = v.y; a[4*q+2] = v.z; a[4*q+3] = v.w;
        }

        float* gl = g_L + (size_t)m * 1024;
        float mydiag = 1.f;
#pragma unroll
        for (int k = 0; k < 32; k++) {
            float araw = a[k];                  // raw updated column entry (this lane)
            float* cb = colf + ((k & 1) << 5);  // double-buffered column broadcast
            cb[lane] = araw;                    // STS first -> shortest critical path
            __syncwarp();
            float akk  = cb[k];                 // broadcast scalar LDS (lane k's raw diag)
            float t    = __fdividef(araw, akk); // raw/akk for deferred-normalized update
            float rinv = rsqrtf(akk);           // off critical path
            float lik  = araw * rinv;           // normalized entry; lane==k -> sqrt(akk)
            if (lane < k) lik = 0.f;
            if (lane == k) mydiag = lik;
            a[k] = lik;
            gl[k * 32 + lane] = lik;            // coalesced column-major store of L
            // rank-1 update: a[j] -= t * raw_j  (== l_ik * l_jk). Lanes < k do
            // harmless garbage updates on dead entries.
#pragma unroll
            for (int q = (k + 1) / 4; q < 8; q++) {
                float4 c = ((const float4*)cb)[q];
                if (4*q+0 > k) a[4*q+0] -= t * c.x;
                if (4*q+1 > k) a[4*q+1] -= t * c.y;
                if (4*q+2 > k) a[4*q+2] -= t * c.z;
                if (4*q+3 > k) a[4*q+3] -= t * c.w;
            }
        }
        float logd = __logf(mydiag);

        // accumulate Log-Cholesky coords (strict lower + logd in diag slot)
#pragma unroll
        for (int j = 0; j < 32; j++) {
            float v = (j < lane) ? a[j] : ((j == lane) ? logd : 0.f);
            acc[j] += v;
            accsq  += v * v;
        }
    }

    // block reduction: reuse sbuf as sred (tiles dead now)
    __syncthreads();
    float* sred = (float*)sbuf;   // WPB*PART_ENTRIES floats fits in sbuf
#pragma unroll
    for (int j = 0; j < 32; j++)
        sred[wl * PART_ENTRIES + lane * PSTRIDE + j] = acc[j];
    sred[wl * PART_ENTRIES + lane * PSTRIDE + 32] = accsq;
    __syncthreads();

    for (int e = threadIdx.x; e < PART_ENTRIES; e += THREADS) {
        float s = 0.f;
#pragma unroll
        for (int w = 0; w < WPB; w++) s += sred[w * PART_ENTRIES + e];
        g_part[e * BLOCKS + blockIdx.x] = s;   // [entry][block] -> coalesced reduce
    }
}

// ---------------------------------------------------------------------------
// k2a: deterministic tree reduction of 1024 block partials per entry (coalesced).
// ---------------------------------------------------------------------------
__global__ void reduce2a() {
    __shared__ float red[BLOCKS];
    const int e = blockIdx.x;
    red[threadIdx.x] = g_part[e * BLOCKS + threadIdx.x];
    __syncthreads();
#pragma unroll
    for (int s = BLOCKS / 2; s > 0; s >>= 1) {
        if ((int)threadIdx.x < s) red[threadIdx.x] += red[threadIdx.x + s];
        __syncthreads();
    }
    if (threadIdx.x == 0) g_sums[e] = red[0];
}

// ---------------------------------------------------------------------------
// k2b: means, variance = E||x||^2 - ||Ex||^2, factor = s / sqrt(var).
// ---------------------------------------------------------------------------
__global__ void stats_pass(const float* __restrict__ s_in) {
    __shared__ float red[1024];
    const int t = threadIdx.x;               // 1024 threads
    const int i = t >> 5, j = t & 31;
    const float invM = 1.0f / (float)M_TOT;

    float mean = g_sums[i * PSTRIDE + j] * invM;   // 0 for strictly-upper slots
    g_stats[i * 32 + j] = mean;
    float val = -mean * mean;
    if (t < 32) val += g_sums[t * PSTRIDE + 32] * invM;
    red[t] = val;
    __syncthreads();
#pragma unroll
    for (int s = 512; s > 0; s >>= 1) {
        if (t < s) red[t] += red[t + s];
        __syncthreads();
    }
    if (t == 0) {
        float var = red[0];
        g_stats[1024] = s_in[0] / sqrtf(var);
    }
}

// ---------------------------------------------------------------------------
// Pass 3: FUSED load-transform — the centered/rescaled matrix b is computed
// directly while staging L columns into smem (mean applied per float4 chunk,
// diagonal exp-patched by the owning lane). Eliminates the entire b-loop
// (64 scalar LDS + 32 scalar STS per matrix). Syrk + coalesced store as before.
// ---------------------------------------------------------------------------
__global__ void __launch_bounds__(THREADS) out_pass(float* __restrict__ out) {
    __shared__ float4 sbuf[WPB * 288];       // tiles (b matrices)
    __shared__ float  mcol[32 * TS];         // mean, column-major padded: [c*36 + i]
    __shared__ float  smean_d[32];           // logd means
    __shared__ float  sfac;

    for (int e = threadIdx.x; e < 1024; e += THREADS) {
        int i = e >> 5, j = e & 31;          // mean[i][j]
        float v = g_stats[e];
        mcol[j * TS + i] = (i == j) ? 0.f : v;   // diag handled separately
        if (i == j) smean_d[i] = v;
    }
    if (threadIdx.x == 0) sfac = g_stats[1024];
    __syncthreads();
    const float factor = sfac;

    const int lane = threadIdx.x & 31;
    const int wl   = threadIdx.x >> 5;
    float4* tile = sbuf + wl * 288;
    float*  tf   = (float*)tile;
    const float4* mcol4 = (const float4*)mcol;
    const int gw = blockIdx.x * WPB + wl;

    const int rc = lane & 7;                 // row-chunk this lane stages
    const int ch = lane >> 3;                // column subgroup

    for (int m = gw; m < M_TOT; m += NWARPS) {
        // fused load-transform: chunk = rows 4rc..4rc+3 of column c = 4q+ch of L.
        // b = factor*(L - mean); upper triangle stays 0 (L upper = 0, mean
        // strict-upper = 0). Diagonal chunk (q == rc) gets the exp patch.
        const float4* ls = (const float4*)(g_L + (size_t)m * 1024);
#pragma unroll
        for (int q = 0; q < 8; q++) {
            int c = 4 * q + ch;
            float4 v = ls[q * 32 + lane];                    // L rows 4rc.. of col c
            float4 mm = mcol4[c * TS4 + rc];                 // mean, same bank pattern
            float4 b4;
            b4.x = factor * (v.x - mm.x);
            b4.y = factor * (v.y - mm.y);
            b4.z = factor * (v.z - mm.z);
            b4.w = factor * (v.w - mm.w);
            if (q == rc) {                                   // diag row c in this chunk
                float dL = (ch == 0) ? v.x : (ch == 1) ? v.y : (ch == 2) ? v.z : v.w;
                float e  = __expf(factor * (__logf(dL) - smean_d[c]));
                if (ch == 0) b4.x = e; else if (ch == 1) b4.y = e;
                else if (ch == 2) b4.z = e; else b4.w = e;
            }
            tile[c * TS4 + rc] = b4;
        }
        __syncwarp();

        // own b row into registers (stride-1 across lanes: conflict-free)
        float b[32];
#pragma unroll
        for (int j = 0; j < 32; j++) b[j] = tf[j * TS + lane];

        // X_out row i: o[j] = sum_k b_i[k] * b_j[k]; k outer, j chunks of 4
        // (broadcast LDS.128 of column k = {b_j[k]}_j). b[k]=0 for k>lane
        // truncates the row; tile zeros truncate j<k.
        float o[32];
#pragma unroll
        for (int j = 0; j < 32; j++) o[j] = 0.f;
#pragma unroll
        for (int k = 0; k < 32; k++) {
            float bk = b[k];
#pragma unroll
            for (int q = k / 4; q < 8; q++) {
                float4 c = tile[k * TS4 + q];        // b_{4q..4q+3}[k], broadcast
                if (4*q+0 >= k) o[4*q+0] += bk * c.x;
                if (4*q+1 >= k) o[4*q+1] += bk * c.y;
                if (4*q+2 >= k) o[4*q+2] += bk * c.z;
                if (4*q+3 >= k) o[4*q+3] += bk * c.w;
            }
        }
        __syncwarp();   // all tile reads done before restage

        // stage o row-major, then coalesced store
#pragma unroll
        for (int q = 0; q < 8; q++)
            tile[lane * TS4 + q] = make_float4(o[4*q], o[4*q+1], o[4*q+2], o[4*q+3]);
        __syncwarp();
        float4* od = (float4*)(out + (size_t)m * 1024);
#pragma unroll
        for (int q = 0; q < 8; q++)
            od[q * 32 + lane] = tile[(4 * q + (lane >> 3)) * TS4 + (lane & 7)];
        __syncwarp();
    }
}

extern "C" void kernel_launch(void* const* d_in, const int* in_sizes, int n_in,
                              void* d_out, int out_size) {
    const float* X = (const float*)d_in[0];
    const float* s = (const float*)d_in[1];
    float* out = (float*)d_out;

    chol_pass1<<<BLOCKS, THREADS>>>(X);
    reduce2a<<<PART_ENTRIES, BLOCKS>>>();
    stats_pass<<<1, 1024>>>(s);
    out_pass<<<BLOCKS, THREADS>>>(out);
}

// round 16
// speedup vs baseline: 1.1416x; 1.1416x over previous
#include <cuda_runtime.h>
#include <math.h>

// Problem constants
#define M_TOT 32768            // 512*64 matrices
#define BLOCKS 1024
#define THREADS 128
#define WPB 4
#define NWARPS (BLOCKS * WPB)  // 4096 warps -> 8 matrices each
#define TS 36                  // tile row stride in floats (16B-aligned, conflict-free)
#define TS4 9                  // tile row stride in float4
#define PSTRIDE 33             // stats entry stride
#define PART_ENTRIES (32 * PSTRIDE)   // 1056

// Scratch (static device arrays; no runtime allocation allowed)
__device__ float g_L[(size_t)M_TOT * 1024];        // Cholesky factors, COLUMN-major per matrix
__device__ float g_part[PART_ENTRIES * BLOCKS];    // per-block partials, [entry][block]
__device__ float g_sums[PART_ENTRIES];
__device__ float g_stats[1025];                    // mean[32*32] (diag slot = logd mean) + factor

// ---------------------------------------------------------------------------
// Pass 1: DIRECT symmetric load (row i of X == column i, so lane i reads
// a[j] = X[j*32+lane], fully coalesced, no smem transpose), warp-per-matrix
// Cholesky with deferred normalization (raw column broadcast through smem).
// ---------------------------------------------------------------------------
__global__ void __launch_bounds__(THREADS) chol_pass1(const float* __restrict__ X) {
    __shared__ float scol[WPB * 64];     // per warp: 2 x 32 float column broadcast buffers
    __shared__ float sred[WPB * PART_ENTRIES];  // block reduction buffer (16.9 KB)
    const int lane = threadIdx.x & 31;
    const int wl   = threadIdx.x >> 5;
    float* colf = scol + wl * 64;
    const int gw = blockIdx.x * WPB + wl;

    float acc[32];
#pragma unroll
    for (int j = 0; j < 32; j++) acc[j] = 0.f;
    float accsq = 0.f;

    for (int m = gw; m < M_TOT; m += NWARPS) {
        // direct symmetric load: a[j] = X[m][j][lane] == X[m][lane][j]
        const float* xs = X + (size_t)m * 1024;
        float a[32];
#pragma unroll
        for (int j = 0; j < 32; j++) a[j] = xs[j * 32 + lane];

        float* gl = g_L + (size_t)m * 1024;
        float mydiag = 1.f;
#pragma unroll
        for (int k = 0; k < 32; k++) {
            float araw = a[k];                  // raw updated column entry (this lane)
            float* cb = colf + ((k & 1) << 5);  // double-buffered column broadcast
            cb[lane] = araw;                    // STS first -> shortest critical path
            __syncwarp();
            float akk  = cb[k];                 // broadcast scalar LDS (lane k's raw diag)
            float t    = __fdividef(araw, akk); // raw/akk for deferred-normalized update
            float rinv = rsqrtf(akk);           // off critical path
            float lik  = araw * rinv;           // normalized entry; lane==k -> sqrt(akk)
            if (lane < k) lik = 0.f;
            if (lane == k) mydiag = lik;
            a[k] = lik;
            gl[k * 32 + lane] = lik;            // coalesced column-major store of L
            // rank-1 update: a[j] -= t * raw_j  (== l_ik * l_jk). Lanes < k do
            // harmless garbage updates on dead entries.
#pragma unroll
            for (int q = (k + 1) / 4; q < 8; q++) {
                float4 c = ((const float4*)cb)[q];
                if (4*q+0 > k) a[4*q+0] -= t * c.x;
                if (4*q+1 > k) a[4*q+1] -= t * c.y;
                if (4*q+2 > k) a[4*q+2] -= t * c.z;
                if (4*q+3 > k) a[4*q+3] -= t * c.w;
            }
        }
        float logd = __logf(mydiag);

        // accumulate Log-Cholesky coords (strict lower + logd in diag slot)
#pragma unroll
        for (int j = 0; j < 32; j++) {
            float v = (j < lane) ? a[j] : ((j == lane) ? logd : 0.f);
            acc[j] += v;
            accsq  += v * v;
        }
    }

    // block reduction
    __syncthreads();
#pragma unroll
    for (int j = 0; j < 32; j++)
        sred[wl * PART_ENTRIES + lane * PSTRIDE + j] = acc[j];
    sred[wl * PART_ENTRIES + lane * PSTRIDE + 32] = accsq;
    __syncthreads();

    for (int e = threadIdx.x; e < PART_ENTRIES; e += THREADS) {
        float s = 0.f;
#pragma unroll
        for (int w = 0; w < WPB; w++) s += sred[w * PART_ENTRIES + e];
        g_part[e * BLOCKS + blockIdx.x] = s;   // [entry][block] -> coalesced reduce
    }
}

// ---------------------------------------------------------------------------
// k2a: deterministic tree reduction of 1024 block partials per entry (coalesced).
// ---------------------------------------------------------------------------
__global__ void reduce2a() {
    __shared__ float red[BLOCKS];
    const int e = blockIdx.x;
    red[threadIdx.x] = g_part[e * BLOCKS + threadIdx.x];
    __syncthreads();
#pragma unroll
    for (int s = BLOCKS / 2; s > 0; s >>= 1) {
        if ((int)threadIdx.x < s) red[threadIdx.x] += red[threadIdx.x + s];
        __syncthreads();
    }
    if (threadIdx.x == 0) g_sums[e] = red[0];
}

// ---------------------------------------------------------------------------
// k2b: means, variance = E||x||^2 - ||Ex||^2, factor = s / sqrt(var).
// ---------------------------------------------------------------------------
__global__ void stats_pass(const float* __restrict__ s_in) {
    __shared__ float red[1024];
    const int t = threadIdx.x;               // 1024 threads
    const int i = t >> 5, j = t & 31;
    const float invM = 1.0f / (float)M_TOT;

    float mean = g_sums[i * PSTRIDE + j] * invM;   // 0 for strictly-upper slots
    g_stats[i * 32 + j] = mean;
    float val = -mean * mean;
    if (t < 32) val += g_sums[t * PSTRIDE + 32] * invM;
    red[t] = val;
    __syncthreads();
#pragma unroll
    for (int s = 512; s > 0; s >>= 1) {
        if (t < s) red[t] += red[t + s];
        __syncthreads();
    }
    if (t == 0) {
        float var = red[0];
        g_stats[1024] = s_in[0] / sqrtf(var);
    }
}

// ---------------------------------------------------------------------------
// Pass 3: coalesced column-major load of L into smem, center + geodesic
// rescale (R14 b-loop, column-major mean stride 33), L_out L_out^T with
// float4 broadcast reads, then DIRECT symmetric store: X_out row i == column
// i, so out[j*32+lane] = o[j] is fully coalesced with no smem staging.
// ---------------------------------------------------------------------------
__global__ void __launch_bounds__(THREADS) out_pass(float* __restrict__ out) {
    __shared__ float4 sbuf[WPB * 288];       // tiles
    __shared__ float  smean_cm[32 * 33];     // mean, column-major: [j*33 + i]
    __shared__ float  smean_d[32];           // logd means
    __shared__ float  sfac;

    for (int e = threadIdx.x; e < 1024; e += THREADS) {
        int i = e >> 5, j = e & 31;
        float v = g_stats[e];
        smean_cm[j * 33 + i] = (i == j) ? 0.f : v;   // diag handled separately
        if (i == j) smean_d[i] = v;
    }
    if (threadIdx.x == 0) sfac = g_stats[1024];
    __syncthreads();
    const float factor = sfac;

    const int lane = threadIdx.x & 31;
    const int wl   = threadIdx.x >> 5;
    float4* tile = sbuf + wl * 288;
    float*  tf   = (float*)tile;
    const int gw = blockIdx.x * WPB + wl;

    for (int m = gw; m < M_TOT; m += NWARPS) {
        // coalesced load of column-major L -> column-major smem tile tf[col*TS + row]
        const float4* ls = (const float4*)(g_L + (size_t)m * 1024);
#pragma unroll
        for (int q = 0; q < 8; q++) {
            float4 v = ls[q * 32 + lane];    // col 4q+lane/8, rows 4(lane&7)..+3
            tile[(4 * q + (lane >> 3)) * TS4 + (lane & 7)] = v;
        }
        __syncwarp();

        // centered / rescaled own row b (lane i = row i). Upper entries are 0
        // automatically (L upper zeros, mean strict-upper zeros).
        float dL    = tf[lane * TS + lane];          // L[i][i]  (stride-37: conflict-free)
        float mdiag = smean_d[lane];                 // logd mean (stride-1)
        float edc   = __expf(factor * (__logf(dL) - mdiag));
        float b[32];
#pragma unroll
        for (int j = 0; j < 32; j++) {
            float aj = tf[j * TS + lane];            // L[i][j]      (stride-1: conflict-free)
            float mj = smean_cm[j * 33 + lane];      // mean[i][j]   (stride-1: conflict-free)
            float v  = factor * (aj - mj);
            b[j] = (j == lane) ? edc : v;
        }
        // write b back into own column-major slots (only lane i touches (j,i))
#pragma unroll
        for (int j = 0; j < 32; j++) tf[j * TS + lane] = b[j];
        __syncwarp();

        // X_out row i: o[j] = sum_k b_i[k] * b_j[k]; k outer, j chunks of 4
        // (broadcast LDS.128 of column k = {b_j[k]}_j). b[k]=0 for k>lane
        // truncates the row; tile zeros truncate j<k.
        float o[32];
#pragma unroll
        for (int j = 0; j < 32; j++) o[j] = 0.f;
#pragma unroll
        for (int k = 0; k < 32; k++) {
            float bk = b[k];
#pragma unroll
            for (int q = k / 4; q < 8; q++) {
                float4 c = tile[k * TS4 + q];        // b_{4q..4q+3}[k], broadcast
                if (4*q+0 >= k) o[4*q+0] += bk * c.x;
                if (4*q+1 >= k) o[4*q+1] += bk * c.y;
                if (4*q+2 >= k) o[4*q+2] += bk * c.z;
                if (4*q+3 >= k) o[4*q+3] += bk * c.w;
            }
        }
        __syncwarp();   // all tile reads done before next iteration's tile write

        // DIRECT symmetric store: out[m][j][lane] = X_out[j][lane] = X_out[lane][j]
        float* od = out + (size_t)m * 1024;
#pragma unroll
        for (int j = 0; j < 32; j++)
            od[j * 32 + lane] = o[j];
    }
}

extern "C" void kernel_launch(void* const* d_in, const int* in_sizes, int n_in,
                              void* d_out, int out_size) {
    const float* X = (const float*)d_in[0];
    const float* s = (const float*)d_in[1];
    float* out = (float*)d_out;

    chol_pass1<<<BLOCKS, THREADS>>>(X);
    reduce2a<<<PART_ENTRIES, BLOCKS>>>();
    stats_pass<<<1, 1024>>>(s);
    out_pass<<<BLOCKS, THREADS>>>(out);
}